// round 2
// baseline (speedup 1.0000x reference)
#include <cuda_runtime.h>
#include <math.h>

#define N_NODES 16000
#define N_EDGES 256000
#define D 128
#define H 4
#define G3 (3*D)        // 384
#define HD (H*D)        // 512
#define ALPHA 0.2f

// ---------------- static scratch (no allocations allowed) ----------------
__device__ float g_Wh[N_NODES * H * D];       // (n*H+h)*D + d
__device__ float g_ssrc[N_NODES * H];
__device__ float g_sdst[N_NODES * H];
__device__ float g_hprime[N_NODES * H * D];   // == x reshaped (N, 512)
__device__ float g_gi[N_NODES * G3];
__device__ float g_gh[N_NODES * G3];
__device__ int   g_deg[N_NODES];
__device__ int   g_fill[N_NODES];
__device__ int   g_rowptr[N_NODES + 1];
__device__ int   g_csr[N_EDGES];

// ---------------- CSR build ----------------
__global__ void k_init_counts() {
    int i = blockIdx.x * blockDim.x + threadIdx.x;
    if (i < N_NODES) { g_deg[i] = 0; g_fill[i] = 0; }
}

__global__ void k_count(const int* __restrict__ dst) {
    int e = blockIdx.x * blockDim.x + threadIdx.x;
    if (e < N_EDGES) atomicAdd(&g_deg[dst[e]], 1);
}

__global__ void k_scan() {  // single block, 1024 threads
    __shared__ int sh[1024];
    __shared__ int carry_s;
    int t = threadIdx.x;
    if (t == 0) carry_s = 0;
    __syncthreads();
    for (int base = 0; base < N_NODES; base += 1024) {
        int x = (base + t < N_NODES) ? g_deg[base + t] : 0;
        sh[t] = x;
        __syncthreads();
        for (int o = 1; o < 1024; o <<= 1) {
            int add = (t >= o) ? sh[t - o] : 0;
            __syncthreads();
            sh[t] += add;
            __syncthreads();
        }
        int incl = sh[t];
        int carry = carry_s;
        if (base + t < N_NODES) g_rowptr[base + t] = carry + incl - x;
        __syncthreads();
        if (t == 1023) carry_s = carry + incl;
        __syncthreads();
    }
    if (t == 0) g_rowptr[N_NODES] = carry_s;
}

__global__ void k_fill(const int* __restrict__ dst) {
    int e = blockIdx.x * blockDim.x + threadIdx.x;
    if (e < N_EDGES) {
        int d = dst[e];
        int pos = g_rowptr[d] + atomicAdd(&g_fill[d], 1);
        g_csr[pos] = e;
    }
}

// ---------------- K1: Wh[n,h,:] = h[n,:] @ W[h] ----------------
__global__ void __launch_bounds__(256) k_wh(const float* __restrict__ hin,
                                            const float* __restrict__ W) {
    __shared__ float As[64][32];
    __shared__ float Bs[32][128];
    int head = blockIdx.y;
    int row0 = blockIdx.x * 64;
    int tid = threadIdx.x, lane = tid & 31, warp = tid >> 5;
    float acc[8][4] = {};

    #pragma unroll
    for (int kt = 0; kt < D; kt += 32) {
        {
            int r = tid >> 3;
            int c4 = (tid & 7) * 4;
            #pragma unroll
            for (int p = 0; p < 2; p++) {
                *(float4*)&As[r + p * 32][c4] =
                    *(const float4*)&hin[(row0 + r + p * 32) * D + kt + c4];
            }
        }
        {
            const float4* src4 = (const float4*)(W + head * D * D + kt * D);
            float4* dst4 = (float4*)Bs;
            #pragma unroll
            for (int it = 0; it < 4; it++) dst4[tid + it * 256] = src4[tid + it * 256];
        }
        __syncthreads();
        #pragma unroll
        for (int k = 0; k < 32; k++) {
            float4 b = *(const float4*)&Bs[k][lane * 4];
            #pragma unroll
            for (int i = 0; i < 8; i++) {
                float a = As[warp * 8 + i][k];
                acc[i][0] += a * b.x; acc[i][1] += a * b.y;
                acc[i][2] += a * b.z; acc[i][3] += a * b.w;
            }
        }
        __syncthreads();
    }
    #pragma unroll
    for (int i = 0; i < 8; i++) {
        int n = row0 + warp * 8 + i;
        *(float4*)&g_Wh[(n * H + head) * D + lane * 4] =
            make_float4(acc[i][0], acc[i][1], acc[i][2], acc[i][3]);
    }
}

// ---------------- K2: s_src / s_dst ----------------
__global__ void __launch_bounds__(256) k_scores(const float* __restrict__ a) {
    int tid = threadIdx.x, lane = tid & 31, warp = tid >> 5;
    int w = blockIdx.x * 8 + warp;          // w = n*H + head
    int head = w & (H - 1);
    float4 wv = ((const float4*)(g_Wh + w * D))[lane];
    float4 a1 = *(const float4*)&a[head * (2 * D) + lane * 4];
    float4 a2 = *(const float4*)&a[head * (2 * D) + D + lane * 4];
    float d1 = wv.x * a1.x + wv.y * a1.y + wv.z * a1.z + wv.w * a1.w;
    float d2 = wv.x * a2.x + wv.y * a2.y + wv.z * a2.z + wv.w * a2.w;
    #pragma unroll
    for (int o = 16; o; o >>= 1) {
        d1 += __shfl_xor_sync(0xffffffffu, d1, o);
        d2 += __shfl_xor_sync(0xffffffffu, d2, o);
    }
    if (lane == 0) { g_ssrc[w] = d1; g_sdst[w] = d2; }
}

// ---------------- K3: per-(node,head) softmax + aggregate ----------------
__global__ void __launch_bounds__(128) k_agg(const int* __restrict__ src) {
    int n = blockIdx.x;
    int head = threadIdx.x >> 5;
    int lane = threadIdx.x & 31;
    int start = g_rowptr[n], end = g_rowptr[n + 1];
    float4 acc = make_float4(0.f, 0.f, 0.f, 0.f);
    if (end > start) {
        float sd = g_sdst[n * H + head];
        float m = -1e30f;
        for (int j = start + lane; j < end; j += 32) {
            int s = src[g_csr[j]];
            float v = g_ssrc[s * H + head] + sd;
            v = v >= 0.f ? v : ALPHA * v;
            m = fmaxf(m, v);
        }
        #pragma unroll
        for (int o = 16; o; o >>= 1) m = fmaxf(m, __shfl_xor_sync(0xffffffffu, m, o));
        float sum = 0.f;
        for (int j = start + lane; j < end; j += 32) {
            int s = src[g_csr[j]];
            float v = g_ssrc[s * H + head] + sd;
            v = v >= 0.f ? v : ALPHA * v;
            sum += __expf(v - m);
        }
        #pragma unroll
        for (int o = 16; o; o >>= 1) sum += __shfl_xor_sync(0xffffffffu, sum, o);
        float inv = 1.0f / sum;
        for (int j = start; j < end; j++) {
            int s = src[g_csr[j]];
            float v = g_ssrc[s * H + head] + sd;
            v = v >= 0.f ? v : ALPHA * v;
            float att = __expf(v - m) * inv;
            float4 wv = ((const float4*)(g_Wh + (s * H + head) * D))[lane];
            acc.x += att * wv.x; acc.y += att * wv.y;
            acc.z += att * wv.z; acc.w += att * wv.w;
        }
    }
    ((float4*)(g_hprime + (n * H + head) * D))[lane] = acc;
}

// ---------------- K4 body: C[N x 384] = A[N x K] @ B^T + bias ----------------
template<int K>
__device__ __forceinline__ void gemm_bt_body(const float* __restrict__ A,
                                             const float* __restrict__ B,
                                             const float* __restrict__ bias,
                                             float* __restrict__ C) {
    __shared__ float As[64][32];
    __shared__ float Bs[32][132];
    int row0 = blockIdx.x * 64;
    int col0 = blockIdx.y * 128;
    int tid = threadIdx.x, lane = tid & 31, warp = tid >> 5;
    float acc[8][4] = {};

    #pragma unroll
    for (int kt = 0; kt < K; kt += 32) {
        {
            int r = tid >> 3;
            int c4 = (tid & 7) * 4;
            #pragma unroll
            for (int p = 0; p < 2; p++) {
                *(float4*)&As[r + p * 32][c4] =
                    *(const float4*)&A[(row0 + r + p * 32) * K + kt + c4];
            }
        }
        {
            #pragma unroll
            for (int it = 0; it < 4; it++) {
                int idx = tid + it * 256;
                int j = idx >> 3;
                int k4 = (idx & 7) * 4;
                float4 v = *(const float4*)&B[(col0 + j) * K + kt + k4];
                Bs[k4 + 0][j] = v.x; Bs[k4 + 1][j] = v.y;
                Bs[k4 + 2][j] = v.z; Bs[k4 + 3][j] = v.w;
            }
        }
        __syncthreads();
        #pragma unroll
        for (int k = 0; k < 32; k++) {
            float4 b = *(const float4*)&Bs[k][lane * 4];
            #pragma unroll
            for (int i = 0; i < 8; i++) {
                float a = As[warp * 8 + i][k];
                acc[i][0] += a * b.x; acc[i][1] += a * b.y;
                acc[i][2] += a * b.z; acc[i][3] += a * b.w;
            }
        }
        __syncthreads();
    }
    #pragma unroll
    for (int i = 0; i < 8; i++) {
        int row = row0 + warp * 8 + i;
        #pragma unroll
        for (int j = 0; j < 4; j++) {
            int c = col0 + lane * 4 + j;
            C[row * G3 + c] = acc[i][j] + bias[c];
        }
    }
}

// gi = x @ W_ih^T + b_ih  (A = g_hprime, resolved in DEVICE code)
__global__ void __launch_bounds__(256) k_gemm_gi(const float* __restrict__ Wih,
                                                 const float* __restrict__ bih) {
    gemm_bt_body<HD>(g_hprime, Wih, bih, g_gi);
}

// gh = h @ W_hh^T + b_hh  (A = harness pointer, C = g_gh resolved in DEVICE code)
__global__ void __launch_bounds__(256) k_gemm_gh(const float* __restrict__ hin,
                                                 const float* __restrict__ Whh,
                                                 const float* __restrict__ bhh) {
    gemm_bt_body<D>(hin, Whh, bhh, g_gh);
}

// ---------------- K5: GRU elementwise ----------------
__global__ void __launch_bounds__(256) k_gru(const float* __restrict__ hin,
                                             float* __restrict__ out) {
    int idx = blockIdx.x * blockDim.x + threadIdx.x;
    if (idx >= N_NODES * D) return;
    int n = idx >> 7;
    int d = idx & (D - 1);
    float ir = g_gi[n * G3 + d];
    float iz = g_gi[n * G3 + D + d];
    float in_ = g_gi[n * G3 + 2 * D + d];
    float hr = g_gh[n * G3 + d];
    float hz = g_gh[n * G3 + D + d];
    float hn = g_gh[n * G3 + 2 * D + d];
    float r = 1.0f / (1.0f + __expf(-(ir + hr)));
    float z = 1.0f / (1.0f + __expf(-(iz + hz)));
    float nv = tanhf(in_ + r * hn);
    out[idx] = (1.0f - z) * nv + z * hin[idx];
}

// ---------------- launch ----------------
extern "C" void kernel_launch(void* const* d_in, const int* in_sizes, int n_in,
                              void* d_out, int out_size) {
    const float* h_ptr = (const float*)d_in[0];
    const float* W     = (const float*)d_in[1];
    const float* a     = (const float*)d_in[2];
    const float* W_ih  = (const float*)d_in[3];
    const float* W_hh  = (const float*)d_in[4];
    const float* b_ih  = (const float*)d_in[5];
    const float* b_hh  = (const float*)d_in[6];
    const int*   src   = (const int*)d_in[7];
    const int*   dst   = (const int*)d_in[8];
    float* out = (float*)d_out;
    (void)in_sizes; (void)n_in; (void)out_size;

    // CSR build
    k_init_counts<<<(N_NODES + 255) / 256, 256>>>();
    k_count<<<(N_EDGES + 255) / 256, 256>>>(dst);
    k_scan<<<1, 1024>>>();
    k_fill<<<(N_EDGES + 255) / 256, 256>>>(dst);

    // Wh = h @ W[h]
    dim3 g1(N_NODES / 64, H);
    k_wh<<<g1, 256>>>(h_ptr, W);

    // attention scores
    k_scores<<<(N_NODES * H) / 8, 256>>>(a);

    // softmax-aggregate into h'
    k_agg<<<N_NODES, 128>>>(src);

    // gi = x @ W_ih^T + b_ih   (K = 512)
    dim3 g2(N_NODES / 64, 3);
    k_gemm_gi<<<g2, 256>>>(W_ih, b_ih);

    // gh = h @ W_hh^T + b_hh   (K = 128)
    k_gemm_gh<<<g2, 256>>>(h_ptr, W_hh, b_hh);

    // GRU combine
    k_gru<<<(N_NODES * D + 255) / 256, 256>>>(h_ptr, out);
}

// round 6
// speedup vs baseline: 1.3864x; 1.3864x over previous
#include <cuda_runtime.h>
#include <cuda_bf16.h>
#include <mma.h>
#include <math.h>
#include <stdint.h>

using namespace nvcuda;

#define N_NODES 16000
#define N_EDGES 256000
#define D 128
#define H 4
#define G3 (3*D)        // 384
#define HD (H*D)        // 512
#define ALPHA 0.2f

// ---------------- static scratch ----------------
__device__ float g_Wh[N_NODES * H * D];
__device__ float g_ssrc[N_NODES * H];
__device__ float g_sdst[N_NODES * H];
__device__ float g_hprime[N_NODES * H * D];   // x reshaped (N, 512)
__device__ float g_gi[N_NODES * G3];
__device__ float g_gh[N_NODES * G3];
__device__ float g_WT[H * D * D];             // W transposed: [h][e][d]
__device__ int   g_deg[N_NODES];
__device__ int   g_fill[N_NODES];
__device__ int   g_rowptr[N_NODES + 1];
__device__ int   g_csr[N_EDGES];

// split fp32 -> bf16 hi + bf16 lo
__device__ __forceinline__ void split1(float x, __nv_bfloat16& hi, __nv_bfloat16& lo) {
    hi = __float2bfloat16_rn(x);
    lo = __float2bfloat16_rn(x - __bfloat162float(hi));
}

// ---------------- wmma GEMM: C[128 x 128-tile] = A[M,K] @ B[NB,K]^T ----------------
// 3-term bf16 split: C = Ah*Bh + Ah*Bl + Al*Bh  (fp32 accum)
// Block: 256 threads = 8 warps, warp grid 4(m) x 2(n), warp tile 32x64.
template<int KTOT>
__device__ __forceinline__ void tc_gemm_wmma(const float* __restrict__ A,
                                             const float* __restrict__ B,
                                             float* __restrict__ C, int ldC) {
    __shared__ __nv_bfloat16 Ah[128][40];
    __shared__ __nv_bfloat16 Al[128][40];
    __shared__ __nv_bfloat16 Bh[128][40];
    __shared__ __nv_bfloat16 Bl[128][40];

    int tid = threadIdx.x;
    int wid = tid >> 5;
    int warpM = wid >> 1;          // 0..3
    int warpN = wid & 1;           // 0..1
    int row0 = blockIdx.x * 128;

    wmma::fragment<wmma::accumulator, 16, 16, 16, float> acc[2][4];
    #pragma unroll
    for (int i = 0; i < 2; i++)
        #pragma unroll
        for (int j = 0; j < 4; j++)
            wmma::fill_fragment(acc[i][j], 0.0f);

    const int KC = KTOT / 32;
    for (int c = 0; c < KC; c++) {
        // load + split A chunk (128 x 32 floats): 1024 float4 / 256 thr = 4 each
        #pragma unroll
        for (int it = 0; it < 4; it++) {
            int idx = tid + it * 256;
            int r = idx >> 3;
            int c4 = (idx & 7) * 4;
            float4 v = *(const float4*)&A[(size_t)(row0 + r) * KTOT + c * 32 + c4];
            split1(v.x, Ah[r][c4 + 0], Al[r][c4 + 0]);
            split1(v.y, Ah[r][c4 + 1], Al[r][c4 + 1]);
            split1(v.z, Ah[r][c4 + 2], Al[r][c4 + 2]);
            split1(v.w, Ah[r][c4 + 3], Al[r][c4 + 3]);
        }
        // load + split B chunk (128 x 32 floats)
        #pragma unroll
        for (int it = 0; it < 4; it++) {
            int idx = tid + it * 256;
            int r = idx >> 3;
            int c4 = (idx & 7) * 4;
            float4 v = *(const float4*)&B[(size_t)r * KTOT + c * 32 + c4];
            split1(v.x, Bh[r][c4 + 0], Bl[r][c4 + 0]);
            split1(v.y, Bh[r][c4 + 1], Bl[r][c4 + 1]);
            split1(v.z, Bh[r][c4 + 2], Bl[r][c4 + 2]);
            split1(v.w, Bh[r][c4 + 3], Bl[r][c4 + 3]);
        }
        __syncthreads();

        #pragma unroll
        for (int ks = 0; ks < 2; ks++) {
            wmma::fragment<wmma::matrix_a, 16, 16, 16, __nv_bfloat16, wmma::row_major> a_hi[2], a_lo[2];
            #pragma unroll
            for (int fm = 0; fm < 2; fm++) {
                wmma::load_matrix_sync(a_hi[fm], &Ah[warpM * 32 + fm * 16][ks * 16], 40);
                wmma::load_matrix_sync(a_lo[fm], &Al[warpM * 32 + fm * 16][ks * 16], 40);
            }
            #pragma unroll
            for (int fn = 0; fn < 4; fn++) {
                wmma::fragment<wmma::matrix_b, 16, 16, 16, __nv_bfloat16, wmma::col_major> b_hi, b_lo;
                wmma::load_matrix_sync(b_hi, &Bh[warpN * 64 + fn * 16][ks * 16], 40);
                wmma::load_matrix_sync(b_lo, &Bl[warpN * 64 + fn * 16][ks * 16], 40);
                #pragma unroll
                for (int fm = 0; fm < 2; fm++) {
                    wmma::mma_sync(acc[fm][fn], a_hi[fm], b_hi, acc[fm][fn]);
                    wmma::mma_sync(acc[fm][fn], a_hi[fm], b_lo, acc[fm][fn]);
                    wmma::mma_sync(acc[fm][fn], a_lo[fm], b_hi, acc[fm][fn]);
                }
            }
        }
        __syncthreads();
    }

    // epilogue: direct store (bias handled downstream)
    #pragma unroll
    for (int fm = 0; fm < 2; fm++) {
        int row = row0 + warpM * 32 + fm * 16;
        #pragma unroll
        for (int fn = 0; fn < 4; fn++) {
            int col = warpN * 64 + fn * 16;
            wmma::store_matrix_sync(&C[(size_t)row * ldC + col], acc[fm][fn], ldC, wmma::mem_row_major);
        }
    }
}

// Wh[n, head*128 .. ] = h @ W[head]^T' : B = g_WT[head] (128x128, [e][d])
__global__ void __launch_bounds__(256) k_wh_tc(const float* __restrict__ hin) {
    int head = blockIdx.y;
    tc_gemm_wmma<128>(hin, &g_WT[head << 14], &g_Wh[head << 7], HD);
}
// gi = x @ W_ih^T : A = g_hprime (N x 512), B tile = W_ih + col0*512
__global__ void __launch_bounds__(256) k_gi_tc(const float* __restrict__ Wih) {
    int col0 = blockIdx.y * 128;
    tc_gemm_wmma<HD>(g_hprime, Wih + (size_t)col0 * HD, g_gi + col0, G3);
}
// gh = h @ W_hh^T
__global__ void __launch_bounds__(256) k_gh_tc(const float* __restrict__ hin,
                                               const float* __restrict__ Whh) {
    int col0 = blockIdx.y * 128;
    tc_gemm_wmma<D>(hin, Whh + (size_t)col0 * D, g_gh + col0, G3);
}

// ---------------- W transpose: g_WT[h][e][d] = W[h][d][e] ----------------
__global__ void k_transposeW(const float* __restrict__ W) {
    int idx = blockIdx.x * blockDim.x + threadIdx.x;
    if (idx < H * D * D) {
        int h = idx >> 14, rem = idx & 16383, d = rem >> 7, e = rem & 127;
        g_WT[(h << 14) + (e << 7) + d] = W[idx];
    }
}

// ---------------- CSR build ----------------
__global__ void k_init_counts() {
    int i = blockIdx.x * blockDim.x + threadIdx.x;
    if (i < N_NODES) { g_deg[i] = 0; g_fill[i] = 0; }
}
__global__ void k_count(const int* __restrict__ dst) {
    int e = blockIdx.x * blockDim.x + threadIdx.x;
    if (e < N_EDGES) atomicAdd(&g_deg[dst[e]], 1);
}
__global__ void k_scan() {
    __shared__ int sh[1024];
    __shared__ int carry_s;
    int t = threadIdx.x;
    if (t == 0) carry_s = 0;
    __syncthreads();
    for (int base = 0; base < N_NODES; base += 1024) {
        int x = (base + t < N_NODES) ? g_deg[base + t] : 0;
        sh[t] = x;
        __syncthreads();
        for (int o = 1; o < 1024; o <<= 1) {
            int add = (t >= o) ? sh[t - o] : 0;
            __syncthreads();
            sh[t] += add;
            __syncthreads();
        }
        int incl = sh[t];
        int carry = carry_s;
        if (base + t < N_NODES) g_rowptr[base + t] = carry + incl - x;
        __syncthreads();
        if (t == 1023) carry_s = carry + incl;
        __syncthreads();
    }
    if (t == 0) g_rowptr[N_NODES] = carry_s;
}
__global__ void k_fill(const int* __restrict__ dst) {
    int e = blockIdx.x * blockDim.x + threadIdx.x;
    if (e < N_EDGES) {
        int d = dst[e];
        int pos = g_rowptr[d] + atomicAdd(&g_fill[d], 1);
        g_csr[pos] = e;
    }
}

// ---------------- scores ----------------
__global__ void __launch_bounds__(256) k_scores(const float* __restrict__ a) {
    int tid = threadIdx.x, lane = tid & 31, warp = tid >> 5;
    int w = blockIdx.x * 8 + warp;
    int head = w & (H - 1);
    float4 wv = ((const float4*)(g_Wh + w * D))[lane];
    float4 a1 = *(const float4*)&a[head * (2 * D) + lane * 4];
    float4 a2 = *(const float4*)&a[head * (2 * D) + D + lane * 4];
    float d1 = wv.x * a1.x + wv.y * a1.y + wv.z * a1.z + wv.w * a1.w;
    float d2 = wv.x * a2.x + wv.y * a2.y + wv.z * a2.z + wv.w * a2.w;
    #pragma unroll
    for (int o = 16; o; o >>= 1) {
        d1 += __shfl_xor_sync(0xffffffffu, d1, o);
        d2 += __shfl_xor_sync(0xffffffffu, d2, o);
    }
    if (lane == 0) { g_ssrc[w] = d1; g_sdst[w] = d2; }
}

// ---------------- softmax + aggregate ----------------
__global__ void __launch_bounds__(128) k_agg(const int* __restrict__ src) {
    int n = blockIdx.x;
    int head = threadIdx.x >> 5;
    int lane = threadIdx.x & 31;
    int start = g_rowptr[n], end = g_rowptr[n + 1];
    float4 acc = make_float4(0.f, 0.f, 0.f, 0.f);
    if (end > start) {
        float sd = g_sdst[n * H + head];
        float m = -1e30f;
        for (int j = start + lane; j < end; j += 32) {
            int s = src[g_csr[j]];
            float v = g_ssrc[s * H + head] + sd;
            v = v >= 0.f ? v : ALPHA * v;
            m = fmaxf(m, v);
        }
        #pragma unroll
        for (int o = 16; o; o >>= 1) m = fmaxf(m, __shfl_xor_sync(0xffffffffu, m, o));
        float sum = 0.f;
        for (int j = start + lane; j < end; j += 32) {
            int s = src[g_csr[j]];
            float v = g_ssrc[s * H + head] + sd;
            v = v >= 0.f ? v : ALPHA * v;
            sum += __expf(v - m);
        }
        #pragma unroll
        for (int o = 16; o; o >>= 1) sum += __shfl_xor_sync(0xffffffffu, sum, o);
        float inv = 1.0f / sum;
        for (int j = start; j < end; j++) {
            int s = src[g_csr[j]];
            float v = g_ssrc[s * H + head] + sd;
            v = v >= 0.f ? v : ALPHA * v;
            float att = __expf(v - m) * inv;
            float4 wv = ((const float4*)(g_Wh + (s * H + head) * D))[lane];
            acc.x += att * wv.x; acc.y += att * wv.y;
            acc.z += att * wv.z; acc.w += att * wv.w;
        }
    }
    ((float4*)(g_hprime + (n * H + head) * D))[lane] = acc;
}

// ---------------- GRU elementwise (bias folded here) ----------------
__global__ void __launch_bounds__(256) k_gru(const float* __restrict__ hin,
                                             const float* __restrict__ bih,
                                             const float* __restrict__ bhh,
                                             float* __restrict__ out) {
    int idx = blockIdx.x * blockDim.x + threadIdx.x;
    if (idx >= N_NODES * D) return;
    int n = idx >> 7;
    int d = idx & (D - 1);
    float ir = g_gi[n * G3 + d]          + bih[d];
    float iz = g_gi[n * G3 + D + d]      + bih[D + d];
    float in_ = g_gi[n * G3 + 2 * D + d] + bih[2 * D + d];
    float hr = g_gh[n * G3 + d]          + bhh[d];
    float hz = g_gh[n * G3 + D + d]      + bhh[D + d];
    float hn = g_gh[n * G3 + 2 * D + d]  + bhh[2 * D + d];
    float r = 1.0f / (1.0f + __expf(-(ir + hr)));
    float z = 1.0f / (1.0f + __expf(-(iz + hz)));
    float nv = tanhf(in_ + r * hn);
    out[idx] = (1.0f - z) * nv + z * hin[idx];
}

// ---------------- launch ----------------
extern "C" void kernel_launch(void* const* d_in, const int* in_sizes, int n_in,
                              void* d_out, int out_size) {
    const float* h_ptr = (const float*)d_in[0];
    const float* W     = (const float*)d_in[1];
    const float* a     = (const float*)d_in[2];
    const float* W_ih  = (const float*)d_in[3];
    const float* W_hh  = (const float*)d_in[4];
    const float* b_ih  = (const float*)d_in[5];
    const float* b_hh  = (const float*)d_in[6];
    const int*   src   = (const int*)d_in[7];
    const int*   dst   = (const int*)d_in[8];
    float* out = (float*)d_out;
    (void)in_sizes; (void)n_in; (void)out_size;

    // CSR build + W transpose
    k_init_counts<<<(N_NODES + 255) / 256, 256>>>();
    k_count<<<(N_EDGES + 255) / 256, 256>>>(dst);
    k_transposeW<<<(H * D * D + 255) / 256, 256>>>(W);
    k_scan<<<1, 1024>>>();
    k_fill<<<(N_EDGES + 255) / 256, 256>>>(dst);

    // Wh = h @ W[h]  (wmma bf16 3-term)
    dim3 g1(N_NODES / 128, H);
    k_wh_tc<<<g1, 256>>>(h_ptr);

    // attention scores
    k_scores<<<(N_NODES * H) / 8, 256>>>(a);

    // softmax-aggregate into h'
    k_agg<<<N_NODES, 128>>>(src);

    // gi = x @ W_ih^T
    dim3 g2(N_NODES / 128, 3);
    k_gi_tc<<<g2, 256>>>(W_ih);

    // gh = h @ W_hh^T
    k_gh_tc<<<g2, 256>>>(h_ptr, W_hh);

    // GRU combine (+ biases)
    k_gru<<<(N_NODES * D + 255) / 256, 256>>>(h_ptr, b_ih, b_hh, out);
}